// round 13
// baseline (speedup 1.0000x reference)
#include <cuda_runtime.h>
#include <cstdint>

// Embedding gather: out[i, :] = w[x[i], :]
// x: [N=16384] int32, w: [32000, 1024] f32, out: [N, 1024] f32.
//
// Floor established across R1-R11 (~16.9us): steady state = 64MB L2-hit
// reads + 64MB mandatory DRAM writes at the aggregate LTS/HBM ceiling.
//  - __stcs evict-first stores keep w L2-resident (the key win, R2).
//  - Output L2-pinning impossible (carveout=0; device-limit changes banned).
//  - Loads must stay 16B __ldg batched before stores (32B loads -> reg trap).
// R12 micro-lever: halve STG issue count with 32B st.global.cs.v4.b64
// stores (pair adjacent rows' chunks per thread). Loads unchanged.
//
// Layout: 256 threads = 2 halves x 128. Half h owns rows row0+4h..+3; each
// thread owns one 32B chunk (two consecutive float4) of each of its 4 rows.

#define ROW_BYTES 4096
#define THREADS 256
#define ROWS_PER_HALF 4
#define ROWS_PER_BLOCK (2 * ROWS_PER_HALF)   // 8

__device__ __forceinline__ void stcs_32B(char* p, float4 lo, float4 hi) {
    asm volatile("st.global.cs.v4.b64 [%0], {%1,%2,%3,%4};"
                 :: "l"(p),
                    "l"(*(const uint64_t*)&lo.x), "l"(*(const uint64_t*)&lo.z),
                    "l"(*(const uint64_t*)&hi.x), "l"(*(const uint64_t*)&hi.z)
                 : "memory");
}

__global__ __launch_bounds__(THREADS)
void embed_gather_kernel(const int* __restrict__ x,
                         const char* __restrict__ w,
                         char* __restrict__ out,
                         int n_rows)
{
    const int tid  = threadIdx.x;
    const int half = tid >> 7;               // 0 or 1
    const int ctid = tid & 127;              // 32B-chunk index within row
    const size_t chunk_off = (size_t)ctid * 32;

    const int row0 = blockIdx.x * ROWS_PER_BLOCK + half * ROWS_PER_HALF;

    if (row0 + ROWS_PER_HALF <= n_rows) {
        int idx[ROWS_PER_HALF];
#pragma unroll
        for (int r = 0; r < ROWS_PER_HALF; r++)
            idx[r] = __ldg(&x[row0 + r]);

        // 8 independent 16B gather loads (proven MLP profile), all before
        // any store.
        float4 lo[ROWS_PER_HALF], hi[ROWS_PER_HALF];
#pragma unroll
        for (int r = 0; r < ROWS_PER_HALF; r++) {
            const float4* src =
                (const float4*)(w + (size_t)idx[r] * ROW_BYTES + chunk_off);
            lo[r] = __ldg(src);
            hi[r] = __ldg(src + 1);
        }

        // 4 x 32B evict-first streaming stores (half the STG issue count).
#pragma unroll
        for (int r = 0; r < ROWS_PER_HALF; r++)
            stcs_32B(out + (size_t)(row0 + r) * ROW_BYTES + chunk_off,
                     lo[r], hi[r]);
    } else {
        for (int r = 0; r < ROWS_PER_HALF; r++) {
            int row = row0 + r;
            if (row < n_rows) {
                int idx = __ldg(&x[row]);
                const float4* src =
                    (const float4*)(w + (size_t)idx * ROW_BYTES + chunk_off);
                float4 lo = __ldg(src);
                float4 hi = __ldg(src + 1);
                stcs_32B(out + (size_t)row * ROW_BYTES + chunk_off, lo, hi);
            }
        }
    }
}

extern "C" void kernel_launch(void* const* d_in, const int* in_sizes, int n_in,
                              void* d_out, int out_size)
{
    // metadata order: x (int32, B*S = 16384), w (float32, 32000*1024)
    const int* x = (const int*)d_in[0];
    const char* w = (const char*)d_in[1];
    char* out = (char*)d_out;

    const int n_rows = in_sizes[0];              // 16384
    const int grid = (n_rows + ROWS_PER_BLOCK - 1) / ROWS_PER_BLOCK;

    embed_gather_kernel<<<grid, THREADS>>>(x, w, out, n_rows);
}